// round 5
// baseline (speedup 1.0000x reference)
#include <cuda_runtime.h>

// YOLO-style detection loss.
// preds:  (n, 1470) f32  [pcls 980 | pconf 98 | pbox 392]
// labels: (n, 1225) f32  per cell (25 floats): [flag | 20 cls | 4 box]
// Row strides 1470/1225 floats => row bases only 8B-aligned for odd rows.
// All vector loads must be float2 (8B), never float4.

#define L_CELLS 49
#define ROW_P 1470
#define ROW_L 1225
#define NOOBJ_W 0.5f
#define OBJ_W 0.5f
#define CLS_W 0.5f
#define COORD_W 2.5f

#define THREADS 256
#define CPT 4
#define CELLS_PER_BLOCK (THREADS * CPT)
#define NWARPS (THREADS / 32)
#define MAX_BLOCKS 8192

__device__ double   g_partials[MAX_BLOCKS];
__device__ unsigned g_counter = 0;    // self-wrapping; replay-safe

__device__ __forceinline__ void cell_to_il(int cell, int& i, int& l)
{
    i = cell / L_CELLS;
    l = cell - i * L_CELLS;
}

__device__ __forceinline__ float obj_cell_loss(
    const float* __restrict__ preds,
    const float* __restrict__ labels,
    int cell)
{
    int i, l;
    cell_to_il(cell, i, l);
    const float* p  = preds  + (size_t)i * ROW_P;
    const float* lb = labels + (size_t)i * ROW_L + l * 25;

    // ---- issue all loads up front ----
    float2 pc = __ldg(reinterpret_cast<const float2*>(p + 980 + l * 2));

    float tb0 = __ldg(lb + 21);
    float tb1 = __ldg(lb + 22);
    float tb2 = __ldg(lb + 23);
    float tb3 = __ldg(lb + 24);

    const float* pb = p + 1078 + l * 8;       // 8B aligned
    float2 b01 = __ldg(reinterpret_cast<const float2*>(pb + 0));
    float2 b23 = __ldg(reinterpret_cast<const float2*>(pb + 2));
    float2 b45 = __ldg(reinterpret_cast<const float2*>(pb + 4));
    float2 b67 = __ldg(reinterpret_cast<const float2*>(pb + 6));

    // ---- class loss (float2 only; l*20 even -> 8B aligned) ----
    const float* pcl = p + l * 20;
    float cls = 0.0f;
    #pragma unroll
    for (int c = 0; c < 20; c += 2) {
        float2 pv = __ldg(reinterpret_cast<const float2*>(pcl + c));
        float d0 = __ldg(lb + 1 + c) - pv.x;
        float d1 = __ldg(lb + 2 + c) - pv.y;
        cls += d0 * d0 + d1 * d1;
    }
    cls *= CLS_W;

    // transformed: o = [x/S, y/S, w^2, h^2]; t = [x/S, y/S, w, h]
    float o0x = b01.x * (1.0f / 7.0f), o0y = b01.y * (1.0f / 7.0f);
    float o0w = b23.x * b23.x,         o0h = b23.y * b23.y;
    float o1x = b45.x * (1.0f / 7.0f), o1y = b45.y * (1.0f / 7.0f);
    float o1w = b67.x * b67.x,         o1h = b67.y * b67.y;
    float tx = tb0 * (1.0f / 7.0f), ty = tb1 * (1.0f / 7.0f);
    float tw = tb2, th = tb3;

    float iou0, iou1, r0, r1;
    {
        float left   = fmaxf(tx - 0.5f * tw, o0x - 0.5f * o0w);
        float right  = fminf(tx + 0.5f * tw, o0x + 0.5f * o0w);
        float top    = fmaxf(ty - 0.5f * th, o0y - 0.5f * o0h);
        float bottom = fminf(ty + 0.5f * th, o0y + 0.5f * o0h);
        float w = right - left, h = bottom - top;
        bool invalid = (w < 0.0f) || (h < 0.0f);
        float inter = invalid ? 0.0f : w * h;
        float uni = tw * th + o0w * o0h - inter;
        iou0 = invalid ? 0.0f : inter / fmaxf(uni, 1e-12f);
        float d0 = tx - o0x, d1 = ty - o0y, d2 = tw - o0w, d3 = th - o0h;
        r0 = d0 * d0 + d1 * d1 + d2 * d2 + d3 * d3;
    }
    {
        float left   = fmaxf(tx - 0.5f * tw, o1x - 0.5f * o1w);
        float right  = fminf(tx + 0.5f * tw, o1x + 0.5f * o1w);
        float top    = fmaxf(ty - 0.5f * th, o1y - 0.5f * o1h);
        float bottom = fminf(ty + 0.5f * th, o1y + 0.5f * o1h);
        float w = right - left, h = bottom - top;
        bool invalid = (w < 0.0f) || (h < 0.0f);
        float inter = invalid ? 0.0f : w * h;
        float uni = tw * th + o1w * o1h - inter;
        iou1 = invalid ? 0.0f : inter / fmaxf(uni, 1e-12f);
        float d0 = tx - o1x, d1 = ty - o1y, d2 = tw - o1w, d3 = th - o1h;
        r1 = d0 * d0 + d1 * d1 + d2 * d2 + d3 * d3;
    }

    // argmax/argmin first-index tie semantics
    float miou = fmaxf(iou0, iou1);
    int best = (miou > 0.0f) ? ((iou1 > iou0) ? 1 : 0)
                             : ((r1 < r0) ? 1 : 0);

    float best_iou  = best ? iou1 : iou0;
    float conf_best = best ? pc.y : pc.x;
    float dcb = best_iou - conf_best;
    // correction vs unconditional NOOBJ*(cx^2+cy^2) base from phase 1
    float conf_corr = OBJ_W * dcb * dcb - NOOBJ_W * conf_best * conf_best;

    float pbx = best ? b45.x : b01.x;
    float pby = best ? b45.y : b01.y;
    float pbw = best ? b67.x : b23.x;
    float pbh = best ? b67.y : b23.y;
    float st2 = sqrtf(tb2), st3 = sqrtf(tb3);
    float e0 = tb0 - pbx, e1 = tb1 - pby;
    float e2 = st2 - pbw, e3 = st3 - pbh;
    float coord = COORD_W * (e0 * e0 + e1 * e1 + e2 * e2 + e3 * e3);

    return conf_corr + cls + coord;
}

__global__ void __launch_bounds__(THREADS, 6) yolo_loss_kernel(
    const float* __restrict__ preds,
    const float* __restrict__ labels,
    int total_cells,
    float* __restrict__ out)
{
    __shared__ int    s_idx[CELLS_PER_BLOCK];
    __shared__ int    s_wcnt[NWARPS];
    __shared__ double s_red[NWARPS];

    const int tid  = threadIdx.x;
    const int lane = tid & 31;
    const int wid  = tid >> 5;
    const int base = blockIdx.x * CELLS_PER_BLOCK;
    const unsigned lmask = (1u << lane) - 1u;

    // ================= phase 1: flags + pconf, coalesced ====================
    float  flag[CPT];
    float2 pc[CPT];
    unsigned bal[CPT];
    float vbase = 0.0f;
    int wcnt = 0;

    if (base + CELLS_PER_BLOCK <= total_cells) {
        // -------- full block fast path (no bounds predication) --------
        #pragma unroll
        for (int k = 0; k < CPT; k++) {
            int cell = base + k * THREADS + tid;
            int i, l; cell_to_il(cell, i, l);
            flag[k] = __ldg(labels + (size_t)i * ROW_L + l * 25);
            pc[k]   = __ldg(reinterpret_cast<const float2*>(
                            preds + (size_t)i * ROW_P + 980 + l * 2));
        }
        #pragma unroll
        for (int k = 0; k < CPT; k++) {
            vbase += NOOBJ_W * (pc[k].x * pc[k].x + pc[k].y * pc[k].y);
            bal[k] = __ballot_sync(0xffffffffu, flag[k] != 0.0f);
            wcnt  += __popc(bal[k]);
        }
    } else {
        #pragma unroll
        for (int k = 0; k < CPT; k++) {
            int cell = base + k * THREADS + tid;
            bool valid = cell < total_cells;
            int c = valid ? cell : 0;
            int i, l; cell_to_il(c, i, l);
            flag[k] = valid ? __ldg(labels + (size_t)i * ROW_L + l * 25) : 0.0f;
            if (valid) {
                pc[k] = __ldg(reinterpret_cast<const float2*>(
                              preds + (size_t)i * ROW_P + 980 + l * 2));
                vbase += NOOBJ_W * (pc[k].x * pc[k].x + pc[k].y * pc[k].y);
            }
            bal[k] = __ballot_sync(0xffffffffu, valid && (flag[k] != 0.0f));
            wcnt  += __popc(bal[k]);
        }
    }

    if (lane == 0) s_wcnt[wid] = wcnt;
    __syncthreads();

    int woff = 0, total_obj = 0;
    #pragma unroll
    for (int w = 0; w < NWARPS; w++) {
        int c = s_wcnt[w];
        if (w < wid) woff += c;
        total_obj += c;
    }

    int pfx = woff;
    #pragma unroll
    for (int k = 0; k < CPT; k++) {
        bool o = (bal[k] >> lane) & 1u;
        int pos = pfx + __popc(bal[k] & lmask);
        if (o) s_idx[pos] = k * THREADS + tid;
        pfx += __popc(bal[k]);
    }
    __syncthreads();

    // ================= phase 2: dense obj processing ========================
    double vd = (double)vbase;
    for (int t = tid; t < total_obj; t += THREADS)
        vd += (double)obj_cell_loss(preds, labels, base + s_idx[t]);

    // ================= block reduction ======================================
    #pragma unroll
    for (int off = 16; off > 0; off >>= 1)
        vd += __shfl_down_sync(0xffffffffu, vd, off);
    if (lane == 0) s_red[wid] = vd;
    __syncthreads();

    if (wid == 0) {
        double x = (lane < NWARPS) ? s_red[lane] : 0.0;
        #pragma unroll
        for (int off = 4; off > 0; off >>= 1)
            x += __shfl_down_sync(0xffffffffu, x, off);
        if (lane == 0) g_partials[blockIdx.x] = x;
    }
    __syncthreads();

    // ================= fused finalize: last block reduces partials ==========
    __shared__ bool s_last;
    if (tid == 0) {
        __threadfence();
        unsigned old = atomicInc(&g_counter, gridDim.x - 1);
        s_last = (old == gridDim.x - 1);
    }
    __syncthreads();

    if (s_last) {
        __threadfence();
        double s = 0.0;
        for (int i = tid; i < gridDim.x; i += THREADS)
            s += g_partials[i];
        #pragma unroll
        for (int off = 16; off > 0; off >>= 1)
            s += __shfl_down_sync(0xffffffffu, s, off);
        if (lane == 0) s_red[wid] = s;
        __syncthreads();
        if (wid == 0) {
            double x = (lane < NWARPS) ? s_red[lane] : 0.0;
            #pragma unroll
            for (int off = 4; off > 0; off >>= 1)
                x += __shfl_down_sync(0xffffffffu, x, off);
            if (lane == 0) out[0] = (float)x;
        }
    }
}

extern "C" void kernel_launch(void* const* d_in, const int* in_sizes, int n_in,
                              void* d_out, int out_size)
{
    const float* preds  = (const float*)d_in[0];
    const float* labels = (const float*)d_in[1];
    int n = in_sizes[0] / ROW_P;
    int total_cells = n * L_CELLS;

    int blocks = (total_cells + CELLS_PER_BLOCK - 1) / CELLS_PER_BLOCK;
    if (blocks > MAX_BLOCKS) blocks = MAX_BLOCKS;   // n=16384 -> 784 blocks

    yolo_loss_kernel<<<blocks, THREADS>>>(preds, labels, total_cells,
                                          (float*)d_out);
}